// round 11
// baseline (speedup 1.0000x reference)
#include <cuda_runtime.h>
#include <cuda_bf16.h>
#include <math.h>

constexpr int N  = 8388608;              // 2^23 samples (fixed by reference)
constexpr int NK = 8388608;              // 2^23 achievable uniform grid points
constexpr int BSHIFT = 8;                // 256 grid points per bucket
constexpr int NB = NK >> BSHIFT;         // 32768 buckets

constexpr int P_TPB    = 256;
constexpr int P_IPT    = 8;
constexpr int P_BLOCKS = N / (P_TPB * P_IPT);          // 4096

constexpr int B_TPB    = 256;
constexpr int B_BPT    = 2;                            // buckets per thread
constexpr int B_TILE   = B_TPB * B_BPT;                // 512 buckets per block
constexpr int B_BLOCKS = NB / B_TILE;                  // 64 (all resident at once)

// ---------------- static device scratch ------------------------------------
// 16-byte stride per bucket is load-bearing: 8-byte-stride buckets share L2
// chunks and neighbor-bucket REDs serialize (R7 regression, +20us).
__device__ float4 g_hist[NB];            // {sum exp(s), sum e, sum e*s, 0} (512 KB,
                                         //  zero-init; scan kernel re-zeroes each call)
__device__ double g_agg[B_BLOCKS];       // per-block exp-sum aggregates
__device__ double g_part[B_BLOCKS];      // per-block loss partials
__device__ int    g_cnt1;                // aggregate-publish barrier
__device__ int    g_cnt2;                // completion counter (elects last block)

__device__ __forceinline__ int bucket_of(float t) {
    int k = __float2int_rn(t * 83886.08f);              // t * 2^23 / 100
    k = max(0, min(k, NK - 1));
    return (NK - 1 - k) >> BSHIFT;                      // ascending = desc time
}

// One 16-byte vector reduction: hist[b] += {ex, ev, ev*s, 0}
__device__ __forceinline__ void red_v4(float4* addr, float ex, float ev, float es) {
    asm volatile("red.global.add.v4.f32 [%0], {%1, %2, %3, %4};"
                 :: "l"(addr), "f"(ex), "f"(ev), "f"(es), "f"(0.0f) : "memory");
}

// Pass 1: pure load -> compute -> RED (at the REDG spread-address floor).
__global__ __launch_bounds__(P_TPB) void
pass1_kernel(const float* __restrict__ truth,
             const float* __restrict__ scores,
             float4* __restrict__ hist) {
    int base = (blockIdx.x * P_TPB + threadIdx.x) * P_IPT;
    float4 s0 = *reinterpret_cast<const float4*>(scores + base);
    float4 s1 = *reinterpret_cast<const float4*>(scores + base + 4);
    float4 t0 = *reinterpret_cast<const float4*>(truth + 2 * base);       // e t e t
    float4 t1 = *reinterpret_cast<const float4*>(truth + 2 * base + 4);
    float4 t2 = *reinterpret_cast<const float4*>(truth + 2 * base + 8);
    float4 t3 = *reinterpret_cast<const float4*>(truth + 2 * base + 12);

    float ev[8] = {t0.x, t0.z, t1.x, t1.z, t2.x, t2.z, t3.x, t3.z};
    float tm[8] = {t0.y, t0.w, t1.y, t1.w, t2.y, t2.w, t3.y, t3.w};
    float sc[8] = {s0.x, s0.y, s0.z, s0.w, s1.x, s1.y, s1.z, s1.w};

    #pragma unroll
    for (int j = 0; j < 8; ++j) {
        int   b  = bucket_of(tm[j]);
        float ex = __expf(sc[j]);
        red_v4(&hist[b], ex, ev[j], ev[j] * sc[j]);     // ev is exactly 0 or 1
    }
}

__device__ __forceinline__ double warp_incl_scan(double v) {
    #pragma unroll
    for (int d = 1; d < 32; d <<= 1) {
        double u = __shfl_up_sync(0xffffffffu, v, d);
        if ((threadIdx.x & 31) >= d) v += u;
    }
    return v;
}
__device__ __forceinline__ double warp_reduce(double v) {
    #pragma unroll
    for (int d = 16; d > 0; d >>= 1)
        v += __shfl_down_sync(0xffffffffu, v, d);
    return v;
}

// Fused scan: block-local fp64 prefix + cross-block exclusive offset via a
// publish/spin barrier (all 64 blocks co-resident), midpoint-weighted event
// logs minus sum(e*s), histogram re-zero, and final mean — one launch.
// Cross-block prefix is summed in a FIXED order (0..bid-1) => deterministic.
__global__ __launch_bounds__(B_TPB) void
scan_fused(float4* __restrict__ hist, float* __restrict__ out) {
    __shared__ double wsh[B_TPB / 32];
    __shared__ double agg_sh, excl_sh;
    int tid  = threadIdx.x;
    int lane = tid & 31;
    int wid  = tid >> 5;
    int bid  = blockIdx.x;
    int base = bid * B_TILE + tid * B_BPT;

    float4 h0 = hist[base];
    float4 h1 = hist[base + 1];
    double s0 = (double)h0.x, s1 = (double)h1.x;

    // block-local inclusive scan of per-thread sums
    double tsum = s0 + s1;
    double inc  = warp_incl_scan(tsum);
    if (lane == 31) wsh[wid] = inc;
    __syncthreads();
    if (tid < 32) {
        double w  = (tid < B_TPB / 32) ? wsh[tid] : 0.0;
        double wi = warp_incl_scan(w);
        if (tid < B_TPB / 32) wsh[tid] = wi - w;        // exclusive warp offset
        if (tid == B_TPB / 32 - 1) agg_sh = wi;         // block aggregate
    }
    __syncthreads();

    // publish aggregate, wait for all, sum lower aggregates in fixed order
    if (tid == 0) {
        *((volatile double*)&g_agg[bid]) = agg_sh;
        __threadfence();
        atomicAdd(&g_cnt1, 1);
        while (*((volatile int*)&g_cnt1) < B_BLOCKS) { }
        __threadfence();
        double e = 0.0;
        for (int i = 0; i < bid; ++i) e += *((volatile double*)&g_agg[i]);
        excl_sh = e;
    }
    __syncthreads();
    double excl = excl_sh + wsh[wid] + (inc - tsum);

    // midpoint-weighted event log minus sum(e*s)
    double acc = 0.0;
    if (h0.y != 0.0f)
        acc += (double)h0.y * (double)logf((float)(excl + 0.5 * s0));
    acc -= (double)h0.z;
    excl += s0;
    if (h1.y != 0.0f)
        acc += (double)h1.y * (double)logf((float)(excl + 0.5 * s1));
    acc -= (double)h1.z;

    // zero the histogram for the next replay (reads already done)
    float4 z = make_float4(0.f, 0.f, 0.f, 0.f);
    hist[base]     = z;
    hist[base + 1] = z;

    // block reduce
    acc = warp_reduce(acc);
    __syncthreads();
    if (lane == 0) wsh[wid] = acc;
    __syncthreads();

    if (tid == 0) {
        double a = 0.0;
        for (int i = 0; i < B_TPB / 32; ++i) a += wsh[i];
        *((volatile double*)&g_part[bid]) = a;
        __threadfence();
        int done = atomicAdd(&g_cnt2, 1);
        if (done == B_BLOCKS - 1) {                     // last block finishes up
            double tot = 0.0;
            for (int i = 0; i < B_BLOCKS; ++i)          // fixed order: deterministic
                tot += *((volatile double*)&g_part[i]);
            out[0] = (float)(tot / (double)N);
            g_cnt1 = 0;                                 // reset for next replay
            g_cnt2 = 0;
        }
    }
}

extern "C" void kernel_launch(void* const* d_in, const int* in_sizes, int n_in,
                              void* d_out, int out_size) {
    const float* scores;
    const float* truth;
    if (in_sizes[0] == N) {
        scores = (const float*)d_in[0];
        truth  = (const float*)d_in[1];
    } else {
        scores = (const float*)d_in[1];
        truth  = (const float*)d_in[0];
    }
    float* out = (float*)d_out;

    float4* hist;
    cudaGetSymbolAddress((void**)&hist, g_hist);

    // hist is zero on entry: zero-initialized statically, and scan_fused
    // re-zeroes it at the end of every call (stream order guarantees no race).
    pass1_kernel<<<P_BLOCKS, P_TPB>>>(truth, scores, hist);
    scan_fused<<<B_BLOCKS, B_TPB>>>(hist, out);
}

// round 12
// speedup vs baseline: 1.0739x; 1.0739x over previous
#include <cuda_runtime.h>
#include <cuda_bf16.h>
#include <math.h>

constexpr int N  = 8388608;              // 2^23 samples (fixed by reference)
constexpr int NK = 8388608;              // 2^23 achievable uniform grid points
constexpr int BSHIFT = 8;                // 256 grid points per bucket
constexpr int NB = NK >> BSHIFT;         // 32768 buckets

constexpr int P_TPB    = 256;
constexpr int P_IPT    = 8;
constexpr int P_BLOCKS = N / (P_TPB * P_IPT);          // 4096

constexpr int B_TPB    = 256;
constexpr int B_BPT    = 2;                            // buckets per thread
constexpr int B_TILE   = B_TPB * B_BPT;                // 512 buckets per block
constexpr int B_BLOCKS = NB / B_TILE;                  // 64 (all resident at once)

// ---------------- static device scratch ------------------------------------
// 16-byte stride per bucket is load-bearing: 8-byte-stride buckets share L2
// chunks and neighbor-bucket REDs serialize (R7 regression, +20us).
__device__ float4 g_hist[NB];            // {sum exp(s), sum e, sum e*s, 0} (512 KB,
                                         //  zero-init; scan kernel re-zeroes each call)
__device__ double g_agg[B_BLOCKS];       // per-block exp-sum aggregates
__device__ double g_part[B_BLOCKS];      // per-block loss partials
__device__ int    g_cnt1;                // aggregate-publish barrier
__device__ int    g_cnt2;                // completion counter (elects last block)

__device__ __forceinline__ int bucket_of(float t) {
    int k = __float2int_rn(t * 83886.08f);              // t * 2^23 / 100
    k = max(0, min(k, NK - 1));
    return (NK - 1 - k) >> BSHIFT;                      // ascending = desc time
}

// One 16-byte vector reduction: hist[b] += {ex, ev, ev*s, 0}
__device__ __forceinline__ void red_v4(float4* addr, float ex, float ev, float es) {
    asm volatile("red.global.add.v4.f32 [%0], {%1, %2, %3, %4};"
                 :: "l"(addr), "f"(ex), "f"(ev), "f"(es), "f"(0.0f) : "memory");
}

// Pass 1: pure load -> compute -> RED (at the REDG spread-address floor).
__global__ __launch_bounds__(P_TPB) void
pass1_kernel(const float* __restrict__ truth,
             const float* __restrict__ scores,
             float4* __restrict__ hist) {
    int base = (blockIdx.x * P_TPB + threadIdx.x) * P_IPT;
    float4 s0 = *reinterpret_cast<const float4*>(scores + base);
    float4 s1 = *reinterpret_cast<const float4*>(scores + base + 4);
    float4 t0 = *reinterpret_cast<const float4*>(truth + 2 * base);       // e t e t
    float4 t1 = *reinterpret_cast<const float4*>(truth + 2 * base + 4);
    float4 t2 = *reinterpret_cast<const float4*>(truth + 2 * base + 8);
    float4 t3 = *reinterpret_cast<const float4*>(truth + 2 * base + 12);

    float ev[8] = {t0.x, t0.z, t1.x, t1.z, t2.x, t2.z, t3.x, t3.z};
    float tm[8] = {t0.y, t0.w, t1.y, t1.w, t2.y, t2.w, t3.y, t3.w};
    float sc[8] = {s0.x, s0.y, s0.z, s0.w, s1.x, s1.y, s1.z, s1.w};

    #pragma unroll
    for (int j = 0; j < 8; ++j) {
        int   b  = bucket_of(tm[j]);
        float ex = __expf(sc[j]);
        red_v4(&hist[b], ex, ev[j], ev[j] * sc[j]);     // ev is exactly 0 or 1
    }
}

__device__ __forceinline__ double warp_incl_scan(double v) {
    #pragma unroll
    for (int d = 1; d < 32; d <<= 1) {
        double u = __shfl_up_sync(0xffffffffu, v, d);
        if ((threadIdx.x & 31) >= d) v += u;
    }
    return v;
}
__device__ __forceinline__ double warp_reduce(double v) {
    #pragma unroll
    for (int d = 16; d > 0; d >>= 1)
        v += __shfl_down_sync(0xffffffffu, v, d);
    return v;
}
__device__ __forceinline__ double ld_volatile_f64(const double* p) {
    double v;
    asm volatile("ld.volatile.global.f64 %0, [%1];" : "=d"(v) : "l"(p));
    return v;
}

// Fused scan: block-local fp64 prefix + cross-block exclusive offset via a
// publish/spin barrier (all 64 blocks co-resident), midpoint-weighted event
// logs minus sum(e*s), histogram re-zero, and final mean — one launch.
// All cross-block sums use PARALLEL loads + fixed-shape trees (deterministic;
// R11's serial volatile chains on thread 0 cost ~12us of pure L2 latency).
__global__ __launch_bounds__(B_TPB) void
scan_fused(float4* __restrict__ hist, float* __restrict__ out) {
    __shared__ double wsh[B_TPB / 32];
    __shared__ double red_sh[B_BLOCKS / 2];
    __shared__ double agg_sh, excl_sh;
    __shared__ int    last_sh;
    int tid  = threadIdx.x;
    int lane = tid & 31;
    int wid  = tid >> 5;
    int bid  = blockIdx.x;
    int base = bid * B_TILE + tid * B_BPT;

    float4 h0 = hist[base];
    float4 h1 = hist[base + 1];
    double s0 = (double)h0.x, s1 = (double)h1.x;

    // block-local inclusive scan of per-thread sums
    double tsum = s0 + s1;
    double inc  = warp_incl_scan(tsum);
    if (lane == 31) wsh[wid] = inc;
    __syncthreads();
    if (tid < 32) {
        double w  = (tid < B_TPB / 32) ? wsh[tid] : 0.0;
        double wi = warp_incl_scan(w);
        if (tid < B_TPB / 32) wsh[tid] = wi - w;        // exclusive warp offset
        if (tid == B_TPB / 32 - 1) agg_sh = wi;         // block aggregate
    }
    __syncthreads();

    // publish aggregate; thread 0 waits until every block has published
    if (tid == 0) {
        *((volatile double*)&g_agg[bid]) = agg_sh;
        __threadfence();
        atomicAdd(&g_cnt1, 1);
        while (*((volatile int*)&g_cnt1) < B_BLOCKS) { }
        __threadfence();
    }
    __syncthreads();

    // cross-block exclusive offset: 64 parallel loads + fixed-shape tree
    if (tid < B_BLOCKS / 2) {
        double a = (tid       < bid) ? ld_volatile_f64(&g_agg[tid])              : 0.0;
        double b = (tid + 32  < bid) ? ld_volatile_f64(&g_agg[tid + B_BLOCKS/2]) : 0.0;
        double v = warp_reduce(a + b);
        if (tid == 0) excl_sh = v;
    }
    __syncthreads();
    double excl = excl_sh + wsh[wid] + (inc - tsum);

    // midpoint-weighted event log minus sum(e*s)
    double acc = 0.0;
    if (h0.y != 0.0f)
        acc += (double)h0.y * (double)logf((float)(excl + 0.5 * s0));
    acc -= (double)h0.z;
    excl += s0;
    if (h1.y != 0.0f)
        acc += (double)h1.y * (double)logf((float)(excl + 0.5 * s1));
    acc -= (double)h1.z;

    // zero the histogram for the next replay (reads already done)
    float4 z = make_float4(0.f, 0.f, 0.f, 0.f);
    hist[base]     = z;
    hist[base + 1] = z;

    // block reduce of the loss partial
    acc = warp_reduce(acc);
    __syncthreads();
    if (lane == 0) wsh[wid] = acc;
    __syncthreads();
    if (tid < 32) {
        double w = (tid < B_TPB / 32) ? wsh[tid] : 0.0;
        w = warp_reduce(w);
        if (tid == 0) {
            *((volatile double*)&g_part[bid]) = w;
            __threadfence();
            int done = atomicAdd(&g_cnt2, 1);
            last_sh = (done == B_BLOCKS - 1);
        }
    }
    __syncthreads();

    // elected last block: parallel fixed-shape reduction of 64 partials -> mean
    if (last_sh) {
        if (tid < B_BLOCKS / 2) {
            double v = ld_volatile_f64(&g_part[tid])
                     + ld_volatile_f64(&g_part[tid + B_BLOCKS / 2]);
            v = warp_reduce(v);
            if (tid == 0) {
                out[0] = (float)(v / (double)N);
                g_cnt1 = 0;                             // reset for next replay
                g_cnt2 = 0;
            }
        }
    }
}

extern "C" void kernel_launch(void* const* d_in, const int* in_sizes, int n_in,
                              void* d_out, int out_size) {
    const float* scores;
    const float* truth;
    if (in_sizes[0] == N) {
        scores = (const float*)d_in[0];
        truth  = (const float*)d_in[1];
    } else {
        scores = (const float*)d_in[1];
        truth  = (const float*)d_in[0];
    }
    float* out = (float*)d_out;

    float4* hist;
    cudaGetSymbolAddress((void**)&hist, g_hist);

    // hist is zero on entry: zero-initialized statically, and scan_fused
    // re-zeroes it at the end of every call (stream order guarantees no race).
    pass1_kernel<<<P_BLOCKS, P_TPB>>>(truth, scores, hist);
    scan_fused<<<B_BLOCKS, B_TPB>>>(hist, out);
}